// round 7
// baseline (speedup 1.0000x reference)
#include <cuda_runtime.h>

// LieTransport bilinear backward warp — coord pre-pass + span-load gather.
// h_prev: [B=4, C=64, H=128, W=128, R=16] fp32 (64B per (b,c,y,x) vector)
//
// K1 (pre-pass): per output pixel, compute sampling record:
//   rec.x = t_off (y0*W+xs, 14b) | b_off<<14 (y1*W+xs) | edge<<28
//   rec.y = unused; rec.z = bits(wx'); rec.w = bits(wy)
//   where xs = min(x0, W-2); edge (x0==W-1) folds the x-clamp into weights.
// K2 (main): R6 structure — 128B span loads (both x-taps contiguous),
//   y-blend per lane, float4 shfl_xor(4) exchange, x-blend, 128B-line stores.
//   All coordinate math replaced by one broadcast LDG.128 of the record.

#define Hd 128
#define Wd 128
#define Cd 64
#define HWd (Hd * Wd)
#define NPIX (4 * HWd)

__device__ uint4 g_rec[NPIX];   // 1 MB static scratch

// ---- K1: per-pixel sampling record ----
__global__ __launch_bounds__(256) void k_coords(
    const float* __restrict__ flow, const float* __restrict__ dt)
{
    const int pid = blockIdx.x * 256 + threadIdx.x;
    const int b = pid >> 14;
    const int y = (pid >> 7) & (Hd - 1);
    const int x = pid & (Wd - 1);

    const float d  = dt[b];
    const int   fb = ((b * 2) * Hd + y) * Wd + x;
    const float fx = flow[fb];
    const float fy = flow[fb + HWd];

    const float gx = fmaf((float)x, 2.0f / (Wd - 1), -1.0f) - fx * d;
    const float gy = fmaf((float)y, 2.0f / (Hd - 1), -1.0f) - fy * d;

    const float ix = fminf(fmaxf(((gx + 1.0f) * (float)Wd - 1.0f) * 0.5f, 0.0f), (float)(Wd - 1));
    const float iy = fminf(fmaxf(((gy + 1.0f) * (float)Hd - 1.0f) * 0.5f, 0.0f), (float)(Hd - 1));

    const float x0f = floorf(ix);
    const float y0f = floorf(iy);
    const float wx  = ix - x0f;
    const float wy  = iy - y0f;

    const int x0 = (int)x0f;
    const int y0 = (int)y0f;
    const int y1 = min(y0 + 1, Hd - 1);
    const int xs = min(x0, Wd - 2);
    const unsigned edge = (x0 == Wd - 1) ? 1u : 0u;

    uint4 rec;
    rec.x = (unsigned)(y0 * Wd + xs) | ((unsigned)(y1 * Wd + xs) << 14) | (edge << 28);
    rec.y = 0u;
    rec.z = __float_as_uint(wx);
    rec.w = __float_as_uint(wy);
    g_rec[pid] = rec;
}

// ---- K2: main gather ----
__global__ __launch_bounds__(256) void lie_transport_kernel(
    const float4* __restrict__ h4,
    float4*       __restrict__ out4)
{
    const int tid  = threadIdx.x;
    const int lane = tid & 31;
    const int w    = tid >> 5;        // warp 0..7
    const int e    = lane & 7;        // position in 128B span
    const int h    = e >> 2;          // span half (x-tap 0 or 1)
    const int q    = e & 3;           // float4 quarter of R=16
    const int it   = lane >> 3;       // item 0..3
    const int px   = it & 1;          // pixel of pair
    const int k    = it >> 1;         // channel sub-slot 0..1

    const int pp = blockIdx.x;
    const int xp = pp & (Wd / 2 - 1);
    const int y  = (pp >> 6) & (Hd - 1);
    const int b  = pp >> 13;
    const int x  = 2 * xp + px;

    // one broadcast LDG.128: 2 distinct records per block, same 128B line
    const uint4 rec = __ldg(&g_rec[((b * Hd + y) * Wd) + x]);
    const int   t_off = rec.x & 0x3FFF;
    const int   b_off = (rec.x >> 14) & 0x3FFF;
    const bool  edge  = (rec.x >> 28) & 1;
    const float wx    = __uint_as_float(rec.z);
    const float wy    = __uint_as_float(rec.w);

    const float c0 = edge ? 0.0f : (1.0f - wx);
    const float c1 = edge ? 1.0f : wx;
    const float cs = h ? c1 : c0;            // my half's weight
    const float co = h ? c0 : c1;            // other half's weight

    // ---- issue all 8 span loads up front (MLP = 8) ----
    const int plane0 = (b * Cd + (k * 8 + w)) * HWd;   // channel for j=0
    const int tbase  = (plane0 + t_off) * 4 + e;
    const int bbase  = (plane0 + b_off) * 4 + e;
    const int obase  = (plane0 + y * Wd + x) * 4 + q;
    const int jstep  = 16 * HWd * 4;                    // channel += 16 per round

    float4 t[4], bt[4];
#pragma unroll
    for (int j = 0; j < 4; ++j) {
        t[j]  = __ldg(h4 + tbase + j * jstep);
        bt[j] = __ldg(h4 + bbase + j * jstep);
    }

#pragma unroll
    for (int j = 0; j < 4; ++j) {
        float4 m;   // this half-column interpolated in y
        m.x = fmaf(wy, bt[j].x - t[j].x, t[j].x);
        m.y = fmaf(wy, bt[j].y - t[j].y, t[j].y);
        m.z = fmaf(wy, bt[j].z - t[j].z, t[j].z);
        m.w = fmaf(wy, bt[j].w - t[j].w, t[j].w);

        float4 mo;  // other half's column
        mo.x = __shfl_xor_sync(0xffffffffu, m.x, 4);
        mo.y = __shfl_xor_sync(0xffffffffu, m.y, 4);
        mo.z = __shfl_xor_sync(0xffffffffu, m.z, 4);
        mo.w = __shfl_xor_sync(0xffffffffu, m.w, 4);

        float4 r;
        r.x = fmaf(co, mo.x, cs * m.x);
        r.y = fmaf(co, mo.y, cs * m.y);
        r.z = fmaf(co, mo.z, cs * m.z);
        r.w = fmaf(co, mo.w, cs * m.w);

        if (h == 0)
            __stcs(out4 + obase + j * jstep, r);
    }
}

extern "C" void kernel_launch(void* const* d_in, const int* in_sizes, int n_in,
                              void* d_out, int out_size)
{
    const float* h_prev = (const float*)d_in[0];
    const float* flow   = (const float*)d_in[1];
    const float* dt     = (const float*)d_in[2];
    float* out          = (float*)d_out;

    k_coords<<<NPIX / 256, 256>>>(flow, dt);

    const int B = 4;
    dim3 grid(B * Hd * (Wd / 2));   // 32768 blocks, one per pixel pair
    lie_transport_kernel<<<grid, 256>>>((const float4*)h_prev, (float4*)out);
}

// round 8
// speedup vs baseline: 1.0767x; 1.0767x over previous
#include <cuda_runtime.h>

// LieTransport bilinear backward warp — span loads + folded full-warp stores.
// h_prev: [B=4, C=64, H=128, W=128, R=16] fp32 (64B per (b,c,y,x) vector)
//
// R6 structure: taps (y,x0) and (y,x0+1) are contiguous 128B -> one 8-lane
// span load per (row,pixel,channel); y-blend per lane; float4 shfl_xor(4)
// exchanges x-halves; x-blend.
// R8 change: after the butterfly ALL lanes hold the correct result r, so
// stores are folded: per round pair, h==0 lanes store the even round's
// channel and h==1 lanes the odd round's -> 2 full-warp STG.128 per warp
// (was 4 half-predicated), zero divergence, same store wavefronts.

#define Hd 128
#define Wd 128
#define Cd 64
#define HWd (Hd * Wd)

__global__ __launch_bounds__(256) void lie_transport_kernel(
    const float4* __restrict__ h4,
    const float*  __restrict__ flow,
    const float*  __restrict__ dt,
    float4*       __restrict__ out4)
{
    const int tid  = threadIdx.x;
    const int lane = tid & 31;
    const int w    = tid >> 5;        // warp 0..7
    const int e    = lane & 7;        // position in 128B span
    const int h    = e >> 2;          // span half (x-tap 0 or 1)
    const int q    = e & 3;           // float4 quarter of R=16
    const int it   = lane >> 3;       // item 0..3
    const int px   = it & 1;          // pixel of pair
    const int k    = it >> 1;         // channel sub-slot 0..1

    const int pp = blockIdx.x;
    const int xp = pp & (Wd / 2 - 1);
    const int y  = (pp >> 6) & (Hd - 1);
    const int b  = pp >> 13;
    const int x  = 2 * xp + px;

    // ---- sampling coordinates for this thread's pixel ----
    const float d  = dt[b];
    const int   fb = ((b * 2) * Hd + y) * Wd + x;
    const float fx = flow[fb];
    const float fy = flow[fb + HWd];

    const float gx = fmaf((float)x, 2.0f / (Wd - 1), -1.0f) - fx * d;
    const float gy = fmaf((float)y, 2.0f / (Hd - 1), -1.0f) - fy * d;

    const float ix = fminf(fmaxf(((gx + 1.0f) * (float)Wd - 1.0f) * 0.5f, 0.0f), (float)(Wd - 1));
    const float iy = fminf(fmaxf(((gy + 1.0f) * (float)Hd - 1.0f) * 0.5f, 0.0f), (float)(Hd - 1));

    const float x0f = floorf(ix);
    const float y0f = floorf(iy);
    const float wx  = ix - x0f;
    const float wy  = iy - y0f;

    const int x0 = (int)x0f;
    const int y0 = (int)y0f;
    const int y1 = min(y0 + 1, Hd - 1);
    const int xs = min(x0, Wd - 2);          // span start (always in-bounds)

    // x-blend weights per span half; clamp case x0==W-1 -> weights (0,1)
    const bool edge = (x0 == Wd - 1);
    const float c0 = edge ? 0.0f : (1.0f - wx);
    const float c1 = edge ? 1.0f : wx;
    const float cs = h ? c1 : c0;            // my half's weight
    const float co = h ? c0 : c1;            // other half's weight

    // ---- issue all 8 span loads up front (MLP = 8) ----
    const int plane0 = (b * Cd + (k * 8 + w)) * HWd;   // channel for j=0
    const int tbase  = (plane0 + y0 * Wd + xs) * 4 + e;
    const int bbase  = (plane0 + y1 * Wd + xs) * 4 + e;
    const int obase  = (plane0 + y  * Wd + x ) * 4 + q;
    const int jstep  = 16 * HWd * 4;                    // channel += 16 per round

    float4 t[4], bt[4];
#pragma unroll
    for (int j = 0; j < 4; ++j) {
        t[j]  = __ldg(h4 + tbase + j * jstep);
        bt[j] = __ldg(h4 + bbase + j * jstep);
    }

    float4 rprev;
#pragma unroll
    for (int j = 0; j < 4; ++j) {
        float4 m;   // this half-column interpolated in y
        m.x = fmaf(wy, bt[j].x - t[j].x, t[j].x);
        m.y = fmaf(wy, bt[j].y - t[j].y, t[j].y);
        m.z = fmaf(wy, bt[j].z - t[j].z, t[j].z);
        m.w = fmaf(wy, bt[j].w - t[j].w, t[j].w);

        float4 mo;  // other half's column
        mo.x = __shfl_xor_sync(0xffffffffu, m.x, 4);
        mo.y = __shfl_xor_sync(0xffffffffu, m.y, 4);
        mo.z = __shfl_xor_sync(0xffffffffu, m.z, 4);
        mo.w = __shfl_xor_sync(0xffffffffu, m.w, 4);

        float4 r;   // identical in both halves after the butterfly
        r.x = fmaf(co, mo.x, cs * m.x);
        r.y = fmaf(co, mo.y, cs * m.y);
        r.z = fmaf(co, mo.z, cs * m.z);
        r.w = fmaf(co, mo.w, cs * m.w);

        if ((j & 1) == 0) {
            rprev = r;
        } else {
            // folded store: h==0 lanes write round j-1's channel,
            // h==1 lanes write round j's channel. 4 full 128B lines/instr.
            const float4 rv = h ? r : rprev;
            __stcs(out4 + obase + (j - 1 + h) * jstep, rv);
        }
    }
}

extern "C" void kernel_launch(void* const* d_in, const int* in_sizes, int n_in,
                              void* d_out, int out_size)
{
    const float* h_prev = (const float*)d_in[0];
    const float* flow   = (const float*)d_in[1];
    const float* dt     = (const float*)d_in[2];
    float* out          = (float*)d_out;

    const int B = 4;
    dim3 grid(B * Hd * (Wd / 2));   // 32768 blocks, one per pixel pair
    dim3 block(256);

    lie_transport_kernel<<<grid, block>>>(
        (const float4*)h_prev, flow, dt, (float4*)out);
}